// round 8
// baseline (speedup 1.0000x reference)
#include <cuda_runtime.h>

// Problem constants (fixed by reference)
#define BB   2
#define NN   4096
#define DD   128
#define HH   4
#define HID  32
#define EN   16

#define NSPLIT    4    // j-splits for heads attention   (grid = 32*4*8  = 1024 blocks)
#define NSPLIT_L  16   // j-splits for last attention    (grid = 32*16*2 = 1024 blocks)
#define TJ        64   // j tile staged in SMEM
#define WPR       (NN/32)   // 128 mask words per row

// leakyrelu(s)*log2e = C1*s + C2*|s|   (max(s,0.2s) = 0.6s + 0.4|s|)
#define C1f 0.86561702453870f   // 0.6*log2(e)
#define C2f 0.57707801635913f   // 0.4*log2(e)

// ---------------- scratch (device globals; no allocation allowed) ----------------
__device__ __align__(16) unsigned g_bits[(size_t)BB*NN*WPR];          // 4MB adj bitmask
__device__ __align__(16) float g_wh  [BB*HH*NN*HID];
__device__ __align__(16) float g_wh1 [BB*HH*NN];
__device__ __align__(16) float g_wh2 [BB*HH*NN];
__device__ __align__(16) float g_xcat[(size_t)BB*NN*HH*HID];
__device__ __align__(16) float g_whl [BB*NN*EN];
__device__ __align__(16) float g_wh1l[BB*NN];
__device__ __align__(16) float g_wh2l[BB*NN];
__device__ __align__(16) float g_pacc[(size_t)BB*HH*NSPLIT*NN*HID];
__device__ __align__(16) float g_pZ  [BB*HH*NSPLIT*NN];
__device__ __align__(16) float g_paccl[(size_t)BB*NSPLIT_L*NN*EN];
__device__ __align__(16) float g_pZl [BB*NSPLIT_L*NN];

__device__ __forceinline__ float eluf(float x) { return x > 0.f ? x : expm1f(x); }

__device__ __forceinline__ float ex2f(float x) {
    float r; asm("ex2.approx.ftz.f32 %0,%1;" : "=f"(r) : "f"(x)); return r;
}
__device__ __forceinline__ unsigned long long pack2(float p) {
    unsigned long long r; unsigned u = __float_as_uint(p);
    asm("mov.b64 %0,{%1,%1};" : "=l"(r) : "r"(u));
    return r;
}
__device__ __forceinline__ void fma2(unsigned long long& d, unsigned long long a, unsigned long long b) {
    asm("fma.rn.f32x2 %0,%1,%2,%0;" : "+l"(d) : "l"(a), "l"(b));
}

// ---------------- K0: pack adj into bitmask (read adj ONCE from DRAM) ----------------
// warp per row; coalesced float loads + ballot
__global__ void k0_pack(const float* __restrict__ adj) {
    int warp = (blockIdx.x * blockDim.x + threadIdx.x) >> 5;   // over BB*NN rows
    int lane = threadIdx.x & 31;
    const float* row = adj + (size_t)warp * NN;
    unsigned* dst = g_bits + (size_t)warp * WPR;
#pragma unroll 4
    for (int w = 0; w < WPR; w++) {
        float v = row[w * 32 + lane];
        unsigned b = __ballot_sync(0xffffffffu, v != 0.f);
        if (lane == 0) dst[w] = b;
    }
}

// ---------------- K1: wh = fea @ W_h ; wh1 = wh·a[:32] ; wh2 = wh·a[32:] ----------------
__global__ void k1_wh(const float* __restrict__ fea,
                      const float* __restrict__ Wh,
                      const float* __restrict__ ah) {
    int warp = (blockIdx.x * blockDim.x + threadIdx.x) >> 5;
    int lane = threadIdx.x & 31;
    int i  = warp & (NN - 1);
    int bh = warp >> 12;
    int b = bh >> 2, h = bh & 3;

    const float* xrow = fea + ((size_t)b * NN + i) * DD;
    const float* Wp   = Wh + (size_t)h * DD * HID + lane;

    float a0 = 0.f, a1 = 0.f, a2 = 0.f, a3 = 0.f;
#pragma unroll
    for (int k = 0; k < DD; k += 4) {
        float4 xv = *reinterpret_cast<const float4*>(xrow + k);
        a0 += xv.x * Wp[(k + 0) * HID];
        a1 += xv.y * Wp[(k + 1) * HID];
        a2 += xv.z * Wp[(k + 2) * HID];
        a3 += xv.w * Wp[(k + 3) * HID];
    }
    float acc = (a0 + a1) + (a2 + a3);
    g_wh[((size_t)bh * NN + i) * HID + lane] = acc;

    float v1 = acc * ah[h * 2 * HID + lane];
    float v2 = acc * ah[h * 2 * HID + HID + lane];
#pragma unroll
    for (int off = 16; off; off >>= 1) {
        v1 += __shfl_xor_sync(0xffffffffu, v1, off);
        v2 += __shfl_xor_sync(0xffffffffu, v2, off);
    }
    if (lane == 0) { g_wh1[bh * NN + i] = v1; g_wh2[bh * NN + i] = v2; }
}

// ---------------- K2: fused masked-softmax attention (heads), bitmask edition ----------
// 64 threads, 2 rows/thread (128 rows), one (b,h,split); split = 1024 j's.
__global__ __launch_bounds__(64) void k2_att() {
    int bh = blockIdx.z;
    int i0 = blockIdx.x * 128;
    int sp = blockIdx.y;
    int jbase = sp * (NN / NSPLIT);
    int w0 = sp * (NN / NSPLIT / 32);       // 32 words per split
    int t = threadIdx.x;

    __shared__ unsigned mask_s[128][33];          // split's mask words, padded
    __shared__ __align__(16) float wh_s[TJ * HID];
    __shared__ float2 wh2_s[TJ];

    const float* whp = g_wh + (size_t)bh * NN * HID;
    size_t rowbase = (size_t)((bh >> 2) * NN + i0) * WPR;   // bits indexed by (b,row)

    // stage the whole split's mask words: 128 rows x 32 words
#pragma unroll
    for (int k = 0; k < 16; k++) {
        int q = t + k * 64;             // [0,1024)
        int row = q >> 3, c4 = q & 7;
        uint4 v = *reinterpret_cast<const uint4*>(g_bits + rowbase + (size_t)row * WPR + w0 + c4 * 4);
        mask_s[row][c4 * 4 + 0] = v.x; mask_s[row][c4 * 4 + 1] = v.y;
        mask_s[row][c4 * 4 + 2] = v.z; mask_s[row][c4 * 4 + 3] = v.w;
    }

    int r1 = i0 + t, r2 = i0 + 64 + t;
    float wh1a = g_wh1[bh * NN + r1];
    float wh1b = g_wh1[bh * NN + r2];

    unsigned long long acc1[HID / 2] = {}, acc2[HID / 2] = {};
    float Z1 = 0.f, Z2 = 0.f;

    for (int jt = 0; jt < NN / NSPLIT; jt += TJ) {
        int j0 = jbase + jt;
        __syncthreads();
        {   // stage wh tile: 64 x 32 floats = 512 float4
            const float4* src = reinterpret_cast<const float4*>(whp + (size_t)j0 * HID);
            float4* dst = reinterpret_cast<float4*>(wh_s);
#pragma unroll
            for (int k = 0; k < 8; k++) dst[t + k * 64] = src[t + k * 64];
        }
        {   // duplicated wh2 pairs
            float w2 = g_wh2[bh * NN + j0 + t];
            wh2_s[t] = make_float2(w2, w2);
        }
        __syncthreads();

#pragma unroll
        for (int half = 0; half < 2; half++) {
            unsigned m1 = mask_s[t][(jt >> 5) + half];
            unsigned m2 = mask_s[t + 64][(jt >> 5) + half];
#pragma unroll 8
            for (int jj = 0; jj < 32; jj++) {
                int j = half * 32 + jj;
                float2 w2 = wh2_s[j];
                float s1 = wh1a + w2.x;
                float s2 = wh1b + w2.y;
                float e1 = fmaf(C2f, fabsf(s1), C1f * s1);
                float e2 = fmaf(C2f, fabsf(s2), C1f * s2);
                float p1 = (((m1 >> jj) & 1u) && (s1 != 0.f)) ? ex2f(e1) : 0.f;
                float p2 = (((m2 >> jj) & 1u) && (s2 != 0.f)) ? ex2f(e2) : 0.f;
                Z1 += p1; Z2 += p2;
                unsigned long long pp1 = pack2(p1), pp2 = pack2(p2);
                const ulonglong2* wrow = reinterpret_cast<const ulonglong2*>(&wh_s[j * HID]);
#pragma unroll
                for (int cc = 0; cc < HID / 4; cc++) {
                    ulonglong2 w = wrow[cc];
                    fma2(acc1[cc * 2],     pp1, w.x);
                    fma2(acc1[cc * 2 + 1], pp1, w.y);
                    fma2(acc2[cc * 2],     pp2, w.x);
                    fma2(acc2[cc * 2 + 1], pp2, w.y);
                }
            }
        }
    }

    size_t rb1 = ((size_t)(bh * NSPLIT + sp) * NN + r1);
    size_t rb2 = ((size_t)(bh * NSPLIT + sp) * NN + r2);
#pragma unroll
    for (int cc = 0; cc < HID / 2; cc++) {
        *reinterpret_cast<unsigned long long*>(&g_pacc[rb1 * HID + cc * 2]) = acc1[cc];
        *reinterpret_cast<unsigned long long*>(&g_pacc[rb2 * HID + cc * 2]) = acc2[cc];
    }
    g_pZ[rb1] = Z1;
    g_pZ[rb2] = Z2;
}

// ---------------- K2b: combine splits, divide, ELU, write xcat ----------------
__global__ void k2_comb() {
    int idx = blockIdx.x * 256 + threadIdx.x;
    int c  = idx & (HID - 1);
    int ri = idx >> 5;
    int bh = ri >> 12;
    int i  = ri & (NN - 1);
    float a = 0.f, Z = 0.f;
#pragma unroll
    for (int sp = 0; sp < NSPLIT; sp++) {
        size_t rb = ((size_t)(bh * NSPLIT + sp) << 12) + i;
        a += g_pacc[rb * HID + c];
        Z += g_pZ[rb];
    }
    float v = a / Z;
    int b = bh >> 2, h = bh & 3;
    g_xcat[(((size_t)b << 12) + i) * (HH * HID) + h * HID + c] = eluf(v);
}

// ---------------- K3: wh_last = xcat @ W_last ; wh1l/wh2l ----------------
__global__ void k3_whl(const float* __restrict__ Wl, const float* __restrict__ al) {
    int warp = (blockIdx.x * blockDim.x + threadIdx.x) >> 5;
    int lane = threadIdx.x & 31;
    int b = warp >> 12, i = warp & (NN - 1);
    int c = lane & 15, half = lane >> 4;

    const float* xr = g_xcat + ((size_t)b * NN + i) * (HH * HID) + half * 64;
    float a0 = 0.f, a1 = 0.f;
#pragma unroll
    for (int k = 0; k < 64; k += 8) {
        float4 x0 = *reinterpret_cast<const float4*>(xr + k);
        float4 x1 = *reinterpret_cast<const float4*>(xr + k + 4);
        a0 += x0.x * Wl[(half * 64 + k + 0) * EN + c];
        a1 += x0.y * Wl[(half * 64 + k + 1) * EN + c];
        a0 += x0.z * Wl[(half * 64 + k + 2) * EN + c];
        a1 += x0.w * Wl[(half * 64 + k + 3) * EN + c];
        a0 += x1.x * Wl[(half * 64 + k + 4) * EN + c];
        a1 += x1.y * Wl[(half * 64 + k + 5) * EN + c];
        a0 += x1.z * Wl[(half * 64 + k + 6) * EN + c];
        a1 += x1.w * Wl[(half * 64 + k + 7) * EN + c];
    }
    float acc = a0 + a1;
    acc += __shfl_xor_sync(0xffffffffu, acc, 16);
    if (half == 0) g_whl[((size_t)b * NN + i) * EN + c] = acc;

    float v1 = acc * al[c];
    float v2 = acc * al[EN + c];
#pragma unroll
    for (int off = 8; off; off >>= 1) {
        v1 += __shfl_xor_sync(0xffffffffu, v1, off);
        v2 += __shfl_xor_sync(0xffffffffu, v2, off);
    }
    if (lane == 0) { g_wh1l[b * NN + i] = v1; g_wh2l[b * NN + i] = v2; }
}

// ---------------- K4: last-layer fused attention, bitmask edition ----------------
__global__ __launch_bounds__(64) void k4_att() {
    int b  = blockIdx.z;
    int i0 = blockIdx.x * 128;
    int sp = blockIdx.y;
    int jbase = sp * (NN / NSPLIT_L);              // 256 j's
    int w0 = sp * (NN / NSPLIT_L / 32);            // 8 words per split
    int t = threadIdx.x;

    __shared__ unsigned mask_s[128][9];
    __shared__ __align__(16) float wh_s[TJ * EN];
    __shared__ float2 wh2_s[TJ];

    const float* whp = g_whl + (size_t)b * NN * EN;
    size_t rowbase = (size_t)(b * NN + i0) * WPR;

#pragma unroll
    for (int k = 0; k < 4; k++) {
        int q = t + k * 64;             // [0,256): 128 rows x 2 uint4
        int row = q >> 1, c4 = q & 1;
        uint4 v = *reinterpret_cast<const uint4*>(g_bits + rowbase + (size_t)row * WPR + w0 + c4 * 4);
        mask_s[row][c4 * 4 + 0] = v.x; mask_s[row][c4 * 4 + 1] = v.y;
        mask_s[row][c4 * 4 + 2] = v.z; mask_s[row][c4 * 4 + 3] = v.w;
    }

    int r1 = i0 + t, r2 = i0 + 64 + t;
    float wh1a = g_wh1l[b * NN + r1];
    float wh1b = g_wh1l[b * NN + r2];

    unsigned long long acc1[EN / 2] = {}, acc2[EN / 2] = {};
    float Z1 = 0.f, Z2 = 0.f;

    for (int jt = 0; jt < NN / NSPLIT_L; jt += TJ) {   // 4 tiles
        int j0 = jbase + jt;
        __syncthreads();
        {   // stage wh tile: 64 x 16 floats = 256 float4
            const float4* src = reinterpret_cast<const float4*>(whp + (size_t)j0 * EN);
            float4* dst = reinterpret_cast<float4*>(wh_s);
#pragma unroll
            for (int k = 0; k < 4; k++) dst[t + k * 64] = src[t + k * 64];
        }
        {
            float w2 = g_wh2l[b * NN + j0 + t];
            wh2_s[t] = make_float2(w2, w2);
        }
        __syncthreads();

#pragma unroll
        for (int half = 0; half < 2; half++) {
            unsigned m1 = mask_s[t][(jt >> 5) + half];
            unsigned m2 = mask_s[t + 64][(jt >> 5) + half];
#pragma unroll 8
            for (int jj = 0; jj < 32; jj++) {
                int j = half * 32 + jj;
                float2 w2 = wh2_s[j];
                float s1 = wh1a + w2.x;
                float s2 = wh1b + w2.y;
                float e1 = fmaf(C2f, fabsf(s1), C1f * s1);
                float e2 = fmaf(C2f, fabsf(s2), C1f * s2);
                float p1 = (((m1 >> jj) & 1u) && (s1 != 0.f)) ? ex2f(e1) : 0.f;
                float p2 = (((m2 >> jj) & 1u) && (s2 != 0.f)) ? ex2f(e2) : 0.f;
                Z1 += p1; Z2 += p2;
                unsigned long long pp1 = pack2(p1), pp2 = pack2(p2);
                const ulonglong2* wrow = reinterpret_cast<const ulonglong2*>(&wh_s[j * EN]);
#pragma unroll
                for (int cc = 0; cc < EN / 4; cc++) {
                    ulonglong2 w = wrow[cc];
                    fma2(acc1[cc * 2],     pp1, w.x);
                    fma2(acc1[cc * 2 + 1], pp1, w.y);
                    fma2(acc2[cc * 2],     pp2, w.x);
                    fma2(acc2[cc * 2 + 1], pp2, w.y);
                }
            }
        }
    }

    size_t rb1 = ((size_t)(b * NSPLIT_L + sp) * NN + r1);
    size_t rb2 = ((size_t)(b * NSPLIT_L + sp) * NN + r2);
#pragma unroll
    for (int cc = 0; cc < EN / 2; cc++) {
        *reinterpret_cast<unsigned long long*>(&g_paccl[rb1 * EN + cc * 2]) = acc1[cc];
        *reinterpret_cast<unsigned long long*>(&g_paccl[rb2 * EN + cc * 2]) = acc2[cc];
    }
    g_pZl[rb1] = Z1;
    g_pZl[rb2] = Z2;
}

// ---------------- K4b: combine, divide, outer ELU, write output ----------------
__global__ void k4_comb(float* __restrict__ out) {
    int idx = blockIdx.x * 256 + threadIdx.x;
    int c  = idx & (EN - 1);
    int ri = idx >> 4;
    int b  = ri >> 12;
    int i  = ri & (NN - 1);
    float a = 0.f, Z = 0.f;
#pragma unroll
    for (int sp = 0; sp < NSPLIT_L; sp++) {
        size_t rb = ((size_t)(b * NSPLIT_L + sp) << 12) + i;
        a += g_paccl[rb * EN + c];
        Z += g_pZl[rb];
    }
    out[((size_t)b * NN + i) * EN + c] = eluf(a / Z);
}

// ---------------- launch ----------------
extern "C" void kernel_launch(void* const* d_in, const int* in_sizes, int n_in,
                              void* d_out, int out_size) {
    const float* fea = (const float*)d_in[0];   // [B,N,D]
    const float* adj = (const float*)d_in[1];   // [B,N,N]
    const float* Wh  = (const float*)d_in[2];   // [H,D,HID]
    const float* ah  = (const float*)d_in[3];   // [H,2*HID,1]
    const float* Wl  = (const float*)d_in[4];   // [H*HID,EN]
    const float* al  = (const float*)d_in[5];   // [2*EN,1]
    float* out = (float*)d_out;                 // [B,N,EN]

    (void)in_sizes; (void)n_in; (void)out_size;

    k0_pack<<<(BB * NN) / 8, 256>>>(adj);
    k1_wh  <<<(BB * HH * NN) / 8, 256>>>(fea, Wh, ah);
    k2_att <<<dim3(NN / 128, NSPLIT, BB * HH), 64>>>();
    k2_comb<<<(BB * HH * NN * HID) / 256, 256>>>();
    k3_whl <<<(BB * NN) / 8, 256>>>(Wl, al);
    k4_att <<<dim3(NN / 128, NSPLIT_L, BB), 64>>>();
    k4_comb<<<(BB * NN * EN) / 256, 256>>>(out);
}

// round 9
// speedup vs baseline: 1.0006x; 1.0006x over previous
#include <cuda_runtime.h>

// Problem constants (fixed by reference)
#define BB   2
#define NN   4096
#define DD   128
#define HH   4
#define HID  32
#define EN   16

#define NSPLIT    4    // j-splits for heads attention   (grid = 32*4*8  = 1024 blocks)
#define NSPLIT_L  16   // j-splits for last attention    (grid = 32*16*2 = 1024 blocks)
#define TJ        64   // j tile staged in SMEM
#define WPR       (NN/32)   // 128 mask words per row

// leakyrelu(s)*log2e = C1*s + C2*|s|   (max(s,0.2s) = 0.6s + 0.4|s|)
#define C1f 0.86561702453870f   // 0.6*log2(e)
#define C2f 0.57707801635913f   // 0.4*log2(e)

// ---------------- scratch (device globals; no allocation allowed) ----------------
__device__ __align__(16) unsigned g_bits[(size_t)BB*NN*WPR];          // 4MB adj bitmask
__device__ __align__(16) float g_wh  [BB*HH*NN*HID];
__device__ __align__(16) float g_wh1 [BB*HH*NN];
__device__ __align__(16) float g_wh2 [BB*HH*NN];
__device__ __align__(16) float g_xcat[(size_t)BB*NN*HH*HID];
__device__ __align__(16) float g_whl [BB*NN*EN];
__device__ __align__(16) float g_wh1l[BB*NN];
__device__ __align__(16) float g_wh2l[BB*NN];
__device__ __align__(16) float g_pacc[(size_t)BB*HH*NSPLIT*NN*HID];
__device__ __align__(16) float g_pZ  [BB*HH*NSPLIT*NN];
__device__ __align__(16) float g_paccl[(size_t)BB*NSPLIT_L*NN*EN];
__device__ __align__(16) float g_pZl [BB*NSPLIT_L*NN];

__device__ __forceinline__ float eluf(float x) { return x > 0.f ? x : expm1f(x); }

__device__ __forceinline__ float ex2f(float x) {
    float r; asm("ex2.approx.ftz.f32 %0,%1;" : "=f"(r) : "f"(x)); return r;
}
__device__ __forceinline__ unsigned long long pack2(float p) {
    unsigned long long r; unsigned u = __float_as_uint(p);
    asm("mov.b64 %0,{%1,%1};" : "=l"(r) : "r"(u));
    return r;
}
__device__ __forceinline__ void fma2(unsigned long long& d, unsigned long long a, unsigned long long b) {
    asm("fma.rn.f32x2 %0,%1,%2,%0;" : "+l"(d) : "l"(a), "l"(b));
}

// ---------------- K0: pack adj into bitmask (read adj ONCE from DRAM) ----------------
// warp per row; coalesced float loads + ballot
__global__ void k0_pack(const float* __restrict__ adj) {
    int warp = (blockIdx.x * blockDim.x + threadIdx.x) >> 5;   // over BB*NN rows
    int lane = threadIdx.x & 31;
    const float* row = adj + (size_t)warp * NN;
    unsigned* dst = g_bits + (size_t)warp * WPR;
#pragma unroll 4
    for (int w = 0; w < WPR; w++) {
        float v = row[w * 32 + lane];
        unsigned b = __ballot_sync(0xffffffffu, v != 0.f);
        if (lane == 0) dst[w] = b;
    }
}

// ---------------- K1: wh = fea @ W_h ; wh1 = wh·a[:32] ; wh2 = wh·a[32:] ----------------
__global__ void k1_wh(const float* __restrict__ fea,
                      const float* __restrict__ Wh,
                      const float* __restrict__ ah) {
    int warp = (blockIdx.x * blockDim.x + threadIdx.x) >> 5;
    int lane = threadIdx.x & 31;
    int i  = warp & (NN - 1);
    int bh = warp >> 12;
    int b = bh >> 2, h = bh & 3;

    const float* xrow = fea + ((size_t)b * NN + i) * DD;
    const float* Wp   = Wh + (size_t)h * DD * HID + lane;

    float a0 = 0.f, a1 = 0.f, a2 = 0.f, a3 = 0.f;
#pragma unroll
    for (int k = 0; k < DD; k += 4) {
        float4 xv = *reinterpret_cast<const float4*>(xrow + k);
        a0 += xv.x * Wp[(k + 0) * HID];
        a1 += xv.y * Wp[(k + 1) * HID];
        a2 += xv.z * Wp[(k + 2) * HID];
        a3 += xv.w * Wp[(k + 3) * HID];
    }
    float acc = (a0 + a1) + (a2 + a3);
    g_wh[((size_t)bh * NN + i) * HID + lane] = acc;

    float v1 = acc * ah[h * 2 * HID + lane];
    float v2 = acc * ah[h * 2 * HID + HID + lane];
#pragma unroll
    for (int off = 16; off; off >>= 1) {
        v1 += __shfl_xor_sync(0xffffffffu, v1, off);
        v2 += __shfl_xor_sync(0xffffffffu, v2, off);
    }
    if (lane == 0) { g_wh1[bh * NN + i] = v1; g_wh2[bh * NN + i] = v2; }
}

// ---------------- K2: fused masked-softmax attention (heads), bitmask edition ----------
// 64 threads, 2 rows/thread (128 rows), one (b,h,split); split = 1024 j's.
__global__ __launch_bounds__(64) void k2_att() {
    int bh = blockIdx.z;
    int i0 = blockIdx.x * 128;
    int sp = blockIdx.y;
    int jbase = sp * (NN / NSPLIT);
    int w0 = sp * (NN / NSPLIT / 32);       // 32 words per split
    int t = threadIdx.x;

    __shared__ unsigned mask_s[128][33];          // split's mask words, padded
    __shared__ __align__(16) float wh_s[TJ * HID];
    __shared__ float2 wh2_s[TJ];

    const float* whp = g_wh + (size_t)bh * NN * HID;
    size_t rowbase = (size_t)((bh >> 2) * NN + i0) * WPR;   // bits indexed by (b,row)

    // stage the whole split's mask words: 128 rows x 32 words
#pragma unroll
    for (int k = 0; k < 16; k++) {
        int q = t + k * 64;             // [0,1024)
        int row = q >> 3, c4 = q & 7;
        uint4 v = *reinterpret_cast<const uint4*>(g_bits + rowbase + (size_t)row * WPR + w0 + c4 * 4);
        mask_s[row][c4 * 4 + 0] = v.x; mask_s[row][c4 * 4 + 1] = v.y;
        mask_s[row][c4 * 4 + 2] = v.z; mask_s[row][c4 * 4 + 3] = v.w;
    }

    int r1 = i0 + t, r2 = i0 + 64 + t;
    float wh1a = g_wh1[bh * NN + r1];
    float wh1b = g_wh1[bh * NN + r2];

    unsigned long long acc1[HID / 2] = {}, acc2[HID / 2] = {};
    float Z1 = 0.f, Z2 = 0.f;

    for (int jt = 0; jt < NN / NSPLIT; jt += TJ) {
        int j0 = jbase + jt;
        __syncthreads();
        {   // stage wh tile: 64 x 32 floats = 512 float4
            const float4* src = reinterpret_cast<const float4*>(whp + (size_t)j0 * HID);
            float4* dst = reinterpret_cast<float4*>(wh_s);
#pragma unroll
            for (int k = 0; k < 8; k++) dst[t + k * 64] = src[t + k * 64];
        }
        {   // duplicated wh2 pairs
            float w2 = g_wh2[bh * NN + j0 + t];
            wh2_s[t] = make_float2(w2, w2);
        }
        __syncthreads();

#pragma unroll
        for (int half = 0; half < 2; half++) {
            unsigned m1 = mask_s[t][(jt >> 5) + half];
            unsigned m2 = mask_s[t + 64][(jt >> 5) + half];
#pragma unroll 8
            for (int jj = 0; jj < 32; jj++) {
                int j = half * 32 + jj;
                float2 w2 = wh2_s[j];
                float s1 = wh1a + w2.x;
                float s2 = wh1b + w2.y;
                float e1 = fmaf(C2f, fabsf(s1), C1f * s1);
                float e2 = fmaf(C2f, fabsf(s2), C1f * s2);
                float p1 = (((m1 >> jj) & 1u) && (s1 != 0.f)) ? ex2f(e1) : 0.f;
                float p2 = (((m2 >> jj) & 1u) && (s2 != 0.f)) ? ex2f(e2) : 0.f;
                Z1 += p1; Z2 += p2;
                unsigned long long pp1 = pack2(p1), pp2 = pack2(p2);
                const ulonglong2* wrow = reinterpret_cast<const ulonglong2*>(&wh_s[j * HID]);
#pragma unroll
                for (int cc = 0; cc < HID / 4; cc++) {
                    ulonglong2 w = wrow[cc];
                    fma2(acc1[cc * 2],     pp1, w.x);
                    fma2(acc1[cc * 2 + 1], pp1, w.y);
                    fma2(acc2[cc * 2],     pp2, w.x);
                    fma2(acc2[cc * 2 + 1], pp2, w.y);
                }
            }
        }
    }

    size_t rb1 = ((size_t)(bh * NSPLIT + sp) * NN + r1);
    size_t rb2 = ((size_t)(bh * NSPLIT + sp) * NN + r2);
#pragma unroll
    for (int cc = 0; cc < HID / 2; cc++) {
        *reinterpret_cast<unsigned long long*>(&g_pacc[rb1 * HID + cc * 2]) = acc1[cc];
        *reinterpret_cast<unsigned long long*>(&g_pacc[rb2 * HID + cc * 2]) = acc2[cc];
    }
    g_pZ[rb1] = Z1;
    g_pZ[rb2] = Z2;
}

// ---------------- K2b: combine splits, divide, ELU, write xcat ----------------
__global__ void k2_comb() {
    int idx = blockIdx.x * 256 + threadIdx.x;
    int c  = idx & (HID - 1);
    int ri = idx >> 5;
    int bh = ri >> 12;
    int i  = ri & (NN - 1);
    float a = 0.f, Z = 0.f;
#pragma unroll
    for (int sp = 0; sp < NSPLIT; sp++) {
        size_t rb = ((size_t)(bh * NSPLIT + sp) << 12) + i;
        a += g_pacc[rb * HID + c];
        Z += g_pZ[rb];
    }
    float v = a / Z;
    int b = bh >> 2, h = bh & 3;
    g_xcat[(((size_t)b << 12) + i) * (HH * HID) + h * HID + c] = eluf(v);
}

// ---------------- K3: wh_last = xcat @ W_last ; wh1l/wh2l ----------------
__global__ void k3_whl(const float* __restrict__ Wl, const float* __restrict__ al) {
    int warp = (blockIdx.x * blockDim.x + threadIdx.x) >> 5;
    int lane = threadIdx.x & 31;
    int b = warp >> 12, i = warp & (NN - 1);
    int c = lane & 15, half = lane >> 4;

    const float* xr = g_xcat + ((size_t)b * NN + i) * (HH * HID) + half * 64;
    float a0 = 0.f, a1 = 0.f;
#pragma unroll
    for (int k = 0; k < 64; k += 8) {
        float4 x0 = *reinterpret_cast<const float4*>(xr + k);
        float4 x1 = *reinterpret_cast<const float4*>(xr + k + 4);
        a0 += x0.x * Wl[(half * 64 + k + 0) * EN + c];
        a1 += x0.y * Wl[(half * 64 + k + 1) * EN + c];
        a0 += x0.z * Wl[(half * 64 + k + 2) * EN + c];
        a1 += x0.w * Wl[(half * 64 + k + 3) * EN + c];
        a0 += x1.x * Wl[(half * 64 + k + 4) * EN + c];
        a1 += x1.y * Wl[(half * 64 + k + 5) * EN + c];
        a0 += x1.z * Wl[(half * 64 + k + 6) * EN + c];
        a1 += x1.w * Wl[(half * 64 + k + 7) * EN + c];
    }
    float acc = a0 + a1;
    acc += __shfl_xor_sync(0xffffffffu, acc, 16);
    if (half == 0) g_whl[((size_t)b * NN + i) * EN + c] = acc;

    float v1 = acc * al[c];
    float v2 = acc * al[EN + c];
#pragma unroll
    for (int off = 8; off; off >>= 1) {
        v1 += __shfl_xor_sync(0xffffffffu, v1, off);
        v2 += __shfl_xor_sync(0xffffffffu, v2, off);
    }
    if (lane == 0) { g_wh1l[b * NN + i] = v1; g_wh2l[b * NN + i] = v2; }
}

// ---------------- K4: last-layer fused attention, bitmask edition ----------------
__global__ __launch_bounds__(64) void k4_att() {
    int b  = blockIdx.z;
    int i0 = blockIdx.x * 128;
    int sp = blockIdx.y;
    int jbase = sp * (NN / NSPLIT_L);              // 256 j's
    int w0 = sp * (NN / NSPLIT_L / 32);            // 8 words per split
    int t = threadIdx.x;

    __shared__ unsigned mask_s[128][9];
    __shared__ __align__(16) float wh_s[TJ * EN];
    __shared__ float2 wh2_s[TJ];

    const float* whp = g_whl + (size_t)b * NN * EN;
    size_t rowbase = (size_t)(b * NN + i0) * WPR;

#pragma unroll
    for (int k = 0; k < 4; k++) {
        int q = t + k * 64;             // [0,256): 128 rows x 2 uint4
        int row = q >> 1, c4 = q & 1;
        uint4 v = *reinterpret_cast<const uint4*>(g_bits + rowbase + (size_t)row * WPR + w0 + c4 * 4);
        mask_s[row][c4 * 4 + 0] = v.x; mask_s[row][c4 * 4 + 1] = v.y;
        mask_s[row][c4 * 4 + 2] = v.z; mask_s[row][c4 * 4 + 3] = v.w;
    }

    int r1 = i0 + t, r2 = i0 + 64 + t;
    float wh1a = g_wh1l[b * NN + r1];
    float wh1b = g_wh1l[b * NN + r2];

    unsigned long long acc1[EN / 2] = {}, acc2[EN / 2] = {};
    float Z1 = 0.f, Z2 = 0.f;

    for (int jt = 0; jt < NN / NSPLIT_L; jt += TJ) {   // 4 tiles
        int j0 = jbase + jt;
        __syncthreads();
        {   // stage wh tile: 64 x 16 floats = 256 float4
            const float4* src = reinterpret_cast<const float4*>(whp + (size_t)j0 * EN);
            float4* dst = reinterpret_cast<float4*>(wh_s);
#pragma unroll
            for (int k = 0; k < 4; k++) dst[t + k * 64] = src[t + k * 64];
        }
        {
            float w2 = g_wh2l[b * NN + j0 + t];
            wh2_s[t] = make_float2(w2, w2);
        }
        __syncthreads();

#pragma unroll
        for (int half = 0; half < 2; half++) {
            unsigned m1 = mask_s[t][(jt >> 5) + half];
            unsigned m2 = mask_s[t + 64][(jt >> 5) + half];
#pragma unroll 8
            for (int jj = 0; jj < 32; jj++) {
                int j = half * 32 + jj;
                float2 w2 = wh2_s[j];
                float s1 = wh1a + w2.x;
                float s2 = wh1b + w2.y;
                float e1 = fmaf(C2f, fabsf(s1), C1f * s1);
                float e2 = fmaf(C2f, fabsf(s2), C1f * s2);
                float p1 = (((m1 >> jj) & 1u) && (s1 != 0.f)) ? ex2f(e1) : 0.f;
                float p2 = (((m2 >> jj) & 1u) && (s2 != 0.f)) ? ex2f(e2) : 0.f;
                Z1 += p1; Z2 += p2;
                unsigned long long pp1 = pack2(p1), pp2 = pack2(p2);
                const ulonglong2* wrow = reinterpret_cast<const ulonglong2*>(&wh_s[j * EN]);
#pragma unroll
                for (int cc = 0; cc < EN / 4; cc++) {
                    ulonglong2 w = wrow[cc];
                    fma2(acc1[cc * 2],     pp1, w.x);
                    fma2(acc1[cc * 2 + 1], pp1, w.y);
                    fma2(acc2[cc * 2],     pp2, w.x);
                    fma2(acc2[cc * 2 + 1], pp2, w.y);
                }
            }
        }
    }

    size_t rb1 = ((size_t)(b * NSPLIT_L + sp) * NN + r1);
    size_t rb2 = ((size_t)(b * NSPLIT_L + sp) * NN + r2);
#pragma unroll
    for (int cc = 0; cc < EN / 2; cc++) {
        *reinterpret_cast<unsigned long long*>(&g_paccl[rb1 * EN + cc * 2]) = acc1[cc];
        *reinterpret_cast<unsigned long long*>(&g_paccl[rb2 * EN + cc * 2]) = acc2[cc];
    }
    g_pZl[rb1] = Z1;
    g_pZl[rb2] = Z2;
}

// ---------------- K4b: combine, divide, outer ELU, write output ----------------
__global__ void k4_comb(float* __restrict__ out) {
    int idx = blockIdx.x * 256 + threadIdx.x;
    int c  = idx & (EN - 1);
    int ri = idx >> 4;
    int b  = ri >> 12;
    int i  = ri & (NN - 1);
    float a = 0.f, Z = 0.f;
#pragma unroll
    for (int sp = 0; sp < NSPLIT_L; sp++) {
        size_t rb = ((size_t)(b * NSPLIT_L + sp) << 12) + i;
        a += g_paccl[rb * EN + c];
        Z += g_pZl[rb];
    }
    out[((size_t)b * NN + i) * EN + c] = eluf(a / Z);
}

// ---------------- launch ----------------
extern "C" void kernel_launch(void* const* d_in, const int* in_sizes, int n_in,
                              void* d_out, int out_size) {
    const float* fea = (const float*)d_in[0];   // [B,N,D]
    const float* adj = (const float*)d_in[1];   // [B,N,N]
    const float* Wh  = (const float*)d_in[2];   // [H,D,HID]
    const float* ah  = (const float*)d_in[3];   // [H,2*HID,1]
    const float* Wl  = (const float*)d_in[4];   // [H*HID,EN]
    const float* al  = (const float*)d_in[5];   // [2*EN,1]
    float* out = (float*)d_out;                 // [B,N,EN]

    (void)in_sizes; (void)n_in; (void)out_size;

    k0_pack<<<(BB * NN) / 8, 256>>>(adj);
    k1_wh  <<<(BB * HH * NN) / 8, 256>>>(fea, Wh, ah);
    k2_att <<<dim3(NN / 128, NSPLIT, BB * HH), 64>>>();
    k2_comb<<<(BB * HH * NN * HID) / 256, 256>>>();
    k3_whl <<<(BB * NN) / 8, 256>>>(Wl, al);
    k4_att <<<dim3(NN / 128, NSPLIT_L, BB), 64>>>();
    k4_comb<<<(BB * NN * EN) / 256, 256>>>(out);
}

// round 10
// speedup vs baseline: 1.0014x; 1.0008x over previous
#include <cuda_runtime.h>

// Problem constants (fixed by reference)
#define BB   2
#define NN   4096
#define DD   128
#define HH   4
#define HID  32
#define EN   16

#define NSPLIT    4    // j-splits for heads attention   (grid = 32*4*8  = 1024 blocks)
#define NSPLIT_L  16   // j-splits for last attention    (grid = 32*16*2 = 1024 blocks)
#define TJ        64   // j tile staged in SMEM
#define WPR       (NN/32)   // 128 mask words per row

// leakyrelu(s)*log2e = C1*s + C2*|s|   (max(s,0.2s) = 0.6s + 0.4|s|)
#define C1f 0.86561702453870f   // 0.6*log2(e)
#define C2f 0.57707801635913f   // 0.4*log2(e)

// ---------------- scratch (device globals; no allocation allowed) ----------------
__device__ __align__(16) unsigned g_bits[(size_t)BB*NN*WPR];          // 4MB adj bitmask
__device__ __align__(16) float g_wh  [BB*HH*NN*HID];
__device__ __align__(16) float g_wh1 [BB*HH*NN];
__device__ __align__(16) float g_wh2 [BB*HH*NN];
__device__ __align__(16) float g_xcat[(size_t)BB*NN*HH*HID];
__device__ __align__(16) float g_whl [BB*NN*EN];
__device__ __align__(16) float g_wh1l[BB*NN];
__device__ __align__(16) float g_wh2l[BB*NN];
__device__ __align__(16) float g_pacc[(size_t)BB*HH*NSPLIT*NN*HID];
__device__ __align__(16) float g_pZ  [BB*HH*NSPLIT*NN];
__device__ __align__(16) float g_paccl[(size_t)BB*NSPLIT_L*NN*EN];
__device__ __align__(16) float g_pZl [BB*NSPLIT_L*NN];

__device__ __forceinline__ float eluf(float x) { return x > 0.f ? x : expm1f(x); }

__device__ __forceinline__ float ex2f(float x) {
    float r; asm("ex2.approx.ftz.f32 %0,%1;" : "=f"(r) : "f"(x)); return r;
}
__device__ __forceinline__ unsigned long long pack2(float p) {
    unsigned long long r; unsigned u = __float_as_uint(p);
    asm("mov.b64 %0,{%1,%1};" : "=l"(r) : "r"(u));
    return r;
}
__device__ __forceinline__ void fma2(unsigned long long& d, unsigned long long a, unsigned long long b) {
    asm("fma.rn.f32x2 %0,%1,%2,%0;" : "+l"(d) : "l"(a), "l"(b));
}

// ---------------- K0: pack adj into bitmask (read adj ONCE from DRAM) ----------------
// warp per row; coalesced float loads + ballot
__global__ void k0_pack(const float* __restrict__ adj) {
    int warp = (blockIdx.x * blockDim.x + threadIdx.x) >> 5;   // over BB*NN rows
    int lane = threadIdx.x & 31;
    const float* row = adj + (size_t)warp * NN;
    unsigned* dst = g_bits + (size_t)warp * WPR;
#pragma unroll 4
    for (int w = 0; w < WPR; w++) {
        float v = row[w * 32 + lane];
        unsigned b = __ballot_sync(0xffffffffu, v != 0.f);
        if (lane == 0) dst[w] = b;
    }
}

// ---------------- K1: wh = fea @ W_h ; wh1 = wh·a[:32] ; wh2 = wh·a[32:] ----------------
__global__ void k1_wh(const float* __restrict__ fea,
                      const float* __restrict__ Wh,
                      const float* __restrict__ ah) {
    int warp = (blockIdx.x * blockDim.x + threadIdx.x) >> 5;
    int lane = threadIdx.x & 31;
    int i  = warp & (NN - 1);
    int bh = warp >> 12;
    int b = bh >> 2, h = bh & 3;

    const float* xrow = fea + ((size_t)b * NN + i) * DD;
    const float* Wp   = Wh + (size_t)h * DD * HID + lane;

    float a0 = 0.f, a1 = 0.f, a2 = 0.f, a3 = 0.f;
#pragma unroll
    for (int k = 0; k < DD; k += 4) {
        float4 xv = *reinterpret_cast<const float4*>(xrow + k);
        a0 += xv.x * Wp[(k + 0) * HID];
        a1 += xv.y * Wp[(k + 1) * HID];
        a2 += xv.z * Wp[(k + 2) * HID];
        a3 += xv.w * Wp[(k + 3) * HID];
    }
    float acc = (a0 + a1) + (a2 + a3);
    g_wh[((size_t)bh * NN + i) * HID + lane] = acc;

    float v1 = acc * ah[h * 2 * HID + lane];
    float v2 = acc * ah[h * 2 * HID + HID + lane];
#pragma unroll
    for (int off = 16; off; off >>= 1) {
        v1 += __shfl_xor_sync(0xffffffffu, v1, off);
        v2 += __shfl_xor_sync(0xffffffffu, v2, off);
    }
    if (lane == 0) { g_wh1[bh * NN + i] = v1; g_wh2[bh * NN + i] = v2; }
}

// ---------------- K2: fused masked-softmax attention (heads), bitmask edition ----------
// 64 threads, 2 rows/thread (128 rows), one (b,h,split); split = 1024 j's.
__global__ __launch_bounds__(64) void k2_att() {
    int bh = blockIdx.z;
    int i0 = blockIdx.x * 128;
    int sp = blockIdx.y;
    int jbase = sp * (NN / NSPLIT);
    int w0 = sp * (NN / NSPLIT / 32);       // 32 words per split
    int t = threadIdx.x;

    __shared__ unsigned mask_s[128][33];          // split's mask words, padded
    __shared__ __align__(16) float wh_s[TJ * HID];
    __shared__ float2 wh2_s[TJ];

    const float* whp = g_wh + (size_t)bh * NN * HID;
    size_t rowbase = (size_t)((bh >> 2) * NN + i0) * WPR;   // bits indexed by (b,row)

    // stage the whole split's mask words: 128 rows x 32 words
#pragma unroll
    for (int k = 0; k < 16; k++) {
        int q = t + k * 64;             // [0,1024)
        int row = q >> 3, c4 = q & 7;
        uint4 v = *reinterpret_cast<const uint4*>(g_bits + rowbase + (size_t)row * WPR + w0 + c4 * 4);
        mask_s[row][c4 * 4 + 0] = v.x; mask_s[row][c4 * 4 + 1] = v.y;
        mask_s[row][c4 * 4 + 2] = v.z; mask_s[row][c4 * 4 + 3] = v.w;
    }

    int r1 = i0 + t, r2 = i0 + 64 + t;
    float wh1a = g_wh1[bh * NN + r1];
    float wh1b = g_wh1[bh * NN + r2];

    unsigned long long acc1[HID / 2] = {}, acc2[HID / 2] = {};
    float Z1 = 0.f, Z2 = 0.f;

    for (int jt = 0; jt < NN / NSPLIT; jt += TJ) {
        int j0 = jbase + jt;
        __syncthreads();
        {   // stage wh tile: 64 x 32 floats = 512 float4
            const float4* src = reinterpret_cast<const float4*>(whp + (size_t)j0 * HID);
            float4* dst = reinterpret_cast<float4*>(wh_s);
#pragma unroll
            for (int k = 0; k < 8; k++) dst[t + k * 64] = src[t + k * 64];
        }
        {   // duplicated wh2 pairs
            float w2 = g_wh2[bh * NN + j0 + t];
            wh2_s[t] = make_float2(w2, w2);
        }
        __syncthreads();

#pragma unroll
        for (int half = 0; half < 2; half++) {
            unsigned m1 = mask_s[t][(jt >> 5) + half];
            unsigned m2 = mask_s[t + 64][(jt >> 5) + half];
#pragma unroll 8
            for (int jj = 0; jj < 32; jj++) {
                int j = half * 32 + jj;
                float2 w2 = wh2_s[j];
                float s1 = wh1a + w2.x;
                float s2 = wh1b + w2.y;
                float e1 = fmaf(C2f, fabsf(s1), C1f * s1);
                float e2 = fmaf(C2f, fabsf(s2), C1f * s2);
                float p1 = (((m1 >> jj) & 1u) && (s1 != 0.f)) ? ex2f(e1) : 0.f;
                float p2 = (((m2 >> jj) & 1u) && (s2 != 0.f)) ? ex2f(e2) : 0.f;
                Z1 += p1; Z2 += p2;
                unsigned long long pp1 = pack2(p1), pp2 = pack2(p2);
                const ulonglong2* wrow = reinterpret_cast<const ulonglong2*>(&wh_s[j * HID]);
#pragma unroll
                for (int cc = 0; cc < HID / 4; cc++) {
                    ulonglong2 w = wrow[cc];
                    fma2(acc1[cc * 2],     pp1, w.x);
                    fma2(acc1[cc * 2 + 1], pp1, w.y);
                    fma2(acc2[cc * 2],     pp2, w.x);
                    fma2(acc2[cc * 2 + 1], pp2, w.y);
                }
            }
        }
    }

    size_t rb1 = ((size_t)(bh * NSPLIT + sp) * NN + r1);
    size_t rb2 = ((size_t)(bh * NSPLIT + sp) * NN + r2);
#pragma unroll
    for (int cc = 0; cc < HID / 2; cc++) {
        *reinterpret_cast<unsigned long long*>(&g_pacc[rb1 * HID + cc * 2]) = acc1[cc];
        *reinterpret_cast<unsigned long long*>(&g_pacc[rb2 * HID + cc * 2]) = acc2[cc];
    }
    g_pZ[rb1] = Z1;
    g_pZ[rb2] = Z2;
}

// ---------------- K2b: combine splits, divide, ELU, write xcat ----------------
__global__ void k2_comb() {
    int idx = blockIdx.x * 256 + threadIdx.x;
    int c  = idx & (HID - 1);
    int ri = idx >> 5;
    int bh = ri >> 12;
    int i  = ri & (NN - 1);
    float a = 0.f, Z = 0.f;
#pragma unroll
    for (int sp = 0; sp < NSPLIT; sp++) {
        size_t rb = ((size_t)(bh * NSPLIT + sp) << 12) + i;
        a += g_pacc[rb * HID + c];
        Z += g_pZ[rb];
    }
    float v = a / Z;
    int b = bh >> 2, h = bh & 3;
    g_xcat[(((size_t)b << 12) + i) * (HH * HID) + h * HID + c] = eluf(v);
}

// ---------------- K3: wh_last = xcat @ W_last ; wh1l/wh2l ----------------
__global__ void k3_whl(const float* __restrict__ Wl, const float* __restrict__ al) {
    int warp = (blockIdx.x * blockDim.x + threadIdx.x) >> 5;
    int lane = threadIdx.x & 31;
    int b = warp >> 12, i = warp & (NN - 1);
    int c = lane & 15, half = lane >> 4;

    const float* xr = g_xcat + ((size_t)b * NN + i) * (HH * HID) + half * 64;
    float a0 = 0.f, a1 = 0.f;
#pragma unroll
    for (int k = 0; k < 64; k += 8) {
        float4 x0 = *reinterpret_cast<const float4*>(xr + k);
        float4 x1 = *reinterpret_cast<const float4*>(xr + k + 4);
        a0 += x0.x * Wl[(half * 64 + k + 0) * EN + c];
        a1 += x0.y * Wl[(half * 64 + k + 1) * EN + c];
        a0 += x0.z * Wl[(half * 64 + k + 2) * EN + c];
        a1 += x0.w * Wl[(half * 64 + k + 3) * EN + c];
        a0 += x1.x * Wl[(half * 64 + k + 4) * EN + c];
        a1 += x1.y * Wl[(half * 64 + k + 5) * EN + c];
        a0 += x1.z * Wl[(half * 64 + k + 6) * EN + c];
        a1 += x1.w * Wl[(half * 64 + k + 7) * EN + c];
    }
    float acc = a0 + a1;
    acc += __shfl_xor_sync(0xffffffffu, acc, 16);
    if (half == 0) g_whl[((size_t)b * NN + i) * EN + c] = acc;

    float v1 = acc * al[c];
    float v2 = acc * al[EN + c];
#pragma unroll
    for (int off = 8; off; off >>= 1) {
        v1 += __shfl_xor_sync(0xffffffffu, v1, off);
        v2 += __shfl_xor_sync(0xffffffffu, v2, off);
    }
    if (lane == 0) { g_wh1l[b * NN + i] = v1; g_wh2l[b * NN + i] = v2; }
}

// ---------------- K4: last-layer fused attention, bitmask edition ----------------
__global__ __launch_bounds__(64) void k4_att() {
    int b  = blockIdx.z;
    int i0 = blockIdx.x * 128;
    int sp = blockIdx.y;
    int jbase = sp * (NN / NSPLIT_L);              // 256 j's
    int w0 = sp * (NN / NSPLIT_L / 32);            // 8 words per split
    int t = threadIdx.x;

    __shared__ unsigned mask_s[128][9];
    __shared__ __align__(16) float wh_s[TJ * EN];
    __shared__ float2 wh2_s[TJ];

    const float* whp = g_whl + (size_t)b * NN * EN;
    size_t rowbase = (size_t)(b * NN + i0) * WPR;

#pragma unroll
    for (int k = 0; k < 4; k++) {
        int q = t + k * 64;             // [0,256): 128 rows x 2 uint4
        int row = q >> 1, c4 = q & 1;
        uint4 v = *reinterpret_cast<const uint4*>(g_bits + rowbase + (size_t)row * WPR + w0 + c4 * 4);
        mask_s[row][c4 * 4 + 0] = v.x; mask_s[row][c4 * 4 + 1] = v.y;
        mask_s[row][c4 * 4 + 2] = v.z; mask_s[row][c4 * 4 + 3] = v.w;
    }

    int r1 = i0 + t, r2 = i0 + 64 + t;
    float wh1a = g_wh1l[b * NN + r1];
    float wh1b = g_wh1l[b * NN + r2];

    unsigned long long acc1[EN / 2] = {}, acc2[EN / 2] = {};
    float Z1 = 0.f, Z2 = 0.f;

    for (int jt = 0; jt < NN / NSPLIT_L; jt += TJ) {   // 4 tiles
        int j0 = jbase + jt;
        __syncthreads();
        {   // stage wh tile: 64 x 16 floats = 256 float4
            const float4* src = reinterpret_cast<const float4*>(whp + (size_t)j0 * EN);
            float4* dst = reinterpret_cast<float4*>(wh_s);
#pragma unroll
            for (int k = 0; k < 4; k++) dst[t + k * 64] = src[t + k * 64];
        }
        {
            float w2 = g_wh2l[b * NN + j0 + t];
            wh2_s[t] = make_float2(w2, w2);
        }
        __syncthreads();

#pragma unroll
        for (int half = 0; half < 2; half++) {
            unsigned m1 = mask_s[t][(jt >> 5) + half];
            unsigned m2 = mask_s[t + 64][(jt >> 5) + half];
#pragma unroll 8
            for (int jj = 0; jj < 32; jj++) {
                int j = half * 32 + jj;
                float2 w2 = wh2_s[j];
                float s1 = wh1a + w2.x;
                float s2 = wh1b + w2.y;
                float e1 = fmaf(C2f, fabsf(s1), C1f * s1);
                float e2 = fmaf(C2f, fabsf(s2), C1f * s2);
                float p1 = (((m1 >> jj) & 1u) && (s1 != 0.f)) ? ex2f(e1) : 0.f;
                float p2 = (((m2 >> jj) & 1u) && (s2 != 0.f)) ? ex2f(e2) : 0.f;
                Z1 += p1; Z2 += p2;
                unsigned long long pp1 = pack2(p1), pp2 = pack2(p2);
                const ulonglong2* wrow = reinterpret_cast<const ulonglong2*>(&wh_s[j * EN]);
#pragma unroll
                for (int cc = 0; cc < EN / 4; cc++) {
                    ulonglong2 w = wrow[cc];
                    fma2(acc1[cc * 2],     pp1, w.x);
                    fma2(acc1[cc * 2 + 1], pp1, w.y);
                    fma2(acc2[cc * 2],     pp2, w.x);
                    fma2(acc2[cc * 2 + 1], pp2, w.y);
                }
            }
        }
    }

    size_t rb1 = ((size_t)(b * NSPLIT_L + sp) * NN + r1);
    size_t rb2 = ((size_t)(b * NSPLIT_L + sp) * NN + r2);
#pragma unroll
    for (int cc = 0; cc < EN / 2; cc++) {
        *reinterpret_cast<unsigned long long*>(&g_paccl[rb1 * EN + cc * 2]) = acc1[cc];
        *reinterpret_cast<unsigned long long*>(&g_paccl[rb2 * EN + cc * 2]) = acc2[cc];
    }
    g_pZl[rb1] = Z1;
    g_pZl[rb2] = Z2;
}

// ---------------- K4b: combine, divide, outer ELU, write output ----------------
__global__ void k4_comb(float* __restrict__ out) {
    int idx = blockIdx.x * 256 + threadIdx.x;
    int c  = idx & (EN - 1);
    int ri = idx >> 4;
    int b  = ri >> 12;
    int i  = ri & (NN - 1);
    float a = 0.f, Z = 0.f;
#pragma unroll
    for (int sp = 0; sp < NSPLIT_L; sp++) {
        size_t rb = ((size_t)(b * NSPLIT_L + sp) << 12) + i;
        a += g_paccl[rb * EN + c];
        Z += g_pZl[rb];
    }
    out[((size_t)b * NN + i) * EN + c] = eluf(a / Z);
}

// ---------------- launch ----------------
extern "C" void kernel_launch(void* const* d_in, const int* in_sizes, int n_in,
                              void* d_out, int out_size) {
    const float* fea = (const float*)d_in[0];   // [B,N,D]
    const float* adj = (const float*)d_in[1];   // [B,N,N]
    const float* Wh  = (const float*)d_in[2];   // [H,D,HID]
    const float* ah  = (const float*)d_in[3];   // [H,2*HID,1]
    const float* Wl  = (const float*)d_in[4];   // [H*HID,EN]
    const float* al  = (const float*)d_in[5];   // [2*EN,1]
    float* out = (float*)d_out;                 // [B,N,EN]

    (void)in_sizes; (void)n_in; (void)out_size;

    k0_pack<<<(BB * NN) / 8, 256>>>(adj);
    k1_wh  <<<(BB * HH * NN) / 8, 256>>>(fea, Wh, ah);
    k2_att <<<dim3(NN / 128, NSPLIT, BB * HH), 64>>>();
    k2_comb<<<(BB * HH * NN * HID) / 256, 256>>>();
    k3_whl <<<(BB * NN) / 8, 256>>>(Wl, al);
    k4_att <<<dim3(NN / 128, NSPLIT_L, BB), 64>>>();
    k4_comb<<<(BB * NN * EN) / 256, 256>>>(out);
}